// round 3
// baseline (speedup 1.0000x reference)
#include <cuda_runtime.h>

// SGDW: out = p * (1 - LR*WD) - LR * (MOM * v + g)
// LR=0.01, MOM=0.9, WD=0.0001

#define LR    0.01f
#define MOM   0.9f
#define DECAY (1.0f - 0.01f * 0.0001f)

struct Args {
    const float4* p[4];
    const float4* g[4];
    const float4* v[4];
    int off[5];   // cumulative segment boundaries in float4 units; off[0]=0
};

__global__ void __launch_bounds__(256) sgdw_fused_kernel(Args a, int n4)
{
    int i = blockIdx.x * blockDim.x + threadIdx.x;
    if (i >= n4) return;

    // segment select: uniform for all but the 3 boundary warps
    int t = (i >= a.off[1]) + (i >= a.off[2]) + (i >= a.off[3]);
    int j = i - a.off[t];

    float4 pv = __ldg(a.p[t] + j);
    float4 gv = __ldg(a.g[t] + j);
    float4 vv = __ldg(a.v[t] + j);

    float4 o;
    o.x = fmaf(pv.x, DECAY, -LR * fmaf(MOM, vv.x, gv.x));
    o.y = fmaf(pv.y, DECAY, -LR * fmaf(MOM, vv.y, gv.y));
    o.z = fmaf(pv.z, DECAY, -LR * fmaf(MOM, vv.z, gv.z));
    o.w = fmaf(pv.w, DECAY, -LR * fmaf(MOM, vv.w, gv.w));

    ((float4*)nullptr, (void)0);
    reinterpret_cast<float4*>(0);  // no-op (keep compiler honest about aliasing? removed below)
    // direct contiguous store
    // (out pointer passed via grid-constant param below)
}

// NOTE: simpler to pass out separately; rewrite kernel properly:
__global__ void __launch_bounds__(256) sgdw_fused(Args a, float4* __restrict__ out, int n4)
{
    int i = blockIdx.x * blockDim.x + threadIdx.x;
    if (i >= n4) return;

    int t = (i >= a.off[1]) + (i >= a.off[2]) + (i >= a.off[3]);
    int j = i - a.off[t];

    float4 pv = __ldg(a.p[t] + j);
    float4 gv = __ldg(a.g[t] + j);
    float4 vv = __ldg(a.v[t] + j);

    float4 o;
    o.x = fmaf(pv.x, DECAY, -LR * fmaf(MOM, vv.x, gv.x));
    o.y = fmaf(pv.y, DECAY, -LR * fmaf(MOM, vv.y, gv.y));
    o.z = fmaf(pv.z, DECAY, -LR * fmaf(MOM, vv.z, gv.z));
    o.w = fmaf(pv.w, DECAY, -LR * fmaf(MOM, vv.w, gv.w));
    out[i] = o;
}

extern "C" void kernel_launch(void* const* d_in, const int* in_sizes, int n_in,
                              void* d_out, int out_size)
{
    // setup_inputs() inserts p{i}, g{i}, v{i} per tensor -> interleaved order.
    bool interleaved = (in_sizes[0] == in_sizes[1]) && (in_sizes[1] == in_sizes[2]);

    Args a;
    int acc = 0;
    a.off[0] = 0;
    for (int t = 0; t < 4; t++) {
        int n;
        if (interleaved) {
            a.p[t] = (const float4*)d_in[3 * t + 0];
            a.g[t] = (const float4*)d_in[3 * t + 1];
            a.v[t] = (const float4*)d_in[3 * t + 2];
            n = in_sizes[3 * t];
        } else {
            a.p[t] = (const float4*)d_in[t];
            a.g[t] = (const float4*)d_in[4 + t];
            a.v[t] = (const float4*)d_in[8 + t];
            n = in_sizes[t];
        }
        acc += n / 4;
        a.off[t + 1] = acc;
    }
    int n4 = acc;

    int threads = 256;
    int blocks = (n4 + threads - 1) / threads;
    sgdw_fused<<<blocks, threads>>>(a, (float4*)d_out, n4);
}

// round 4
// speedup vs baseline: 2.0544x; 2.0544x over previous
#include <cuda_runtime.h>

// SGDW: out = p * (1 - LR*WD) - LR * (MOM * v + g)
// LR=0.01, MOM=0.9, WD=0.0001

#define LR    0.01f
#define MOM   0.9f
#define DECAY (1.0f - 0.01f * 0.0001f)

__global__ void __launch_bounds__(256)
sgdw_fused(const float4* __restrict__ p0, const float4* __restrict__ g0, const float4* __restrict__ v0,
           const float4* __restrict__ p1, const float4* __restrict__ g1, const float4* __restrict__ v1,
           const float4* __restrict__ p2, const float4* __restrict__ g2, const float4* __restrict__ v2,
           const float4* __restrict__ p3, const float4* __restrict__ g3, const float4* __restrict__ v3,
           float4* __restrict__ out,
           int off1, int off2, int off3, int n4)
{
    int i = blockIdx.x * blockDim.x + threadIdx.x;
    if (i >= n4) return;

    const float4* p;
    const float4* g;
    const float4* v;
    int j;
    if (i < off1)      { p = p0; g = g0; v = v0; j = i; }
    else if (i < off2) { p = p1; g = g1; v = v1; j = i - off1; }
    else if (i < off3) { p = p2; g = g2; v = v2; j = i - off2; }
    else               { p = p3; g = g3; v = v3; j = i - off3; }

    float4 pv = __ldg(p + j);
    float4 gv = __ldg(g + j);
    float4 vv = __ldg(v + j);

    float4 o;
    o.x = fmaf(pv.x, DECAY, -LR * fmaf(MOM, vv.x, gv.x));
    o.y = fmaf(pv.y, DECAY, -LR * fmaf(MOM, vv.y, gv.y));
    o.z = fmaf(pv.z, DECAY, -LR * fmaf(MOM, vv.z, gv.z));
    o.w = fmaf(pv.w, DECAY, -LR * fmaf(MOM, vv.w, gv.w));
    out[i] = o;
}

extern "C" void kernel_launch(void* const* d_in, const int* in_sizes, int n_in,
                              void* d_out, int out_size)
{
    // setup_inputs() inserts p{i}, g{i}, v{i} per tensor -> interleaved order.
    bool il = (in_sizes[0] == in_sizes[1]) && (in_sizes[1] == in_sizes[2]);

    const float4* P[4]; const float4* G[4]; const float4* V[4];
    int off[5];
    off[0] = 0;
    for (int t = 0; t < 4; t++) {
        int n;
        if (il) {
            P[t] = (const float4*)d_in[3 * t + 0];
            G[t] = (const float4*)d_in[3 * t + 1];
            V[t] = (const float4*)d_in[3 * t + 2];
            n = in_sizes[3 * t];
        } else {
            P[t] = (const float4*)d_in[t];
            G[t] = (const float4*)d_in[4 + t];
            V[t] = (const float4*)d_in[8 + t];
            n = in_sizes[t];
        }
        off[t + 1] = off[t] + n / 4;
    }
    int n4 = off[4];

    int threads = 256;
    int blocks = (n4 + threads - 1) / threads;
    sgdw_fused<<<blocks, threads>>>(P[0], G[0], V[0],
                                    P[1], G[1], V[1],
                                    P[2], G[2], V[2],
                                    P[3], G[3], V[3],
                                    (float4*)d_out,
                                    off[1], off[2], off[3], n4);
}